// round 1
// baseline (speedup 1.0000x reference)
#include <cuda_runtime.h>
#include <math.h>

#define NN 2048
#define DD 768
#define LL 16
#define EPSILON 0.3f
#define ALPHA 0.7f

// ---- scratch (device globals; no allocation allowed) ----
__device__ float g_xproj[NN * LL];
__device__ float g_norms[NN];
__device__ float g_pi[NN];
__device__ float g_q[NN];
__device__ float g_v[NN];
__device__ float g_d[NN];
__device__ float g_K[NN * NN];       // 16 MB
__device__ float g_target[NN * DD];  // 6 MB
__device__ float g_S[NN * DD];       // 6 MB

// -------------------- stage 1: x_proj = relu(LN(x @ proj_w + proj_b)) --------------------
__global__ void xproj_kernel(const float* __restrict__ x,
                             const float* __restrict__ pw,
                             const float* __restrict__ pb,
                             const float* __restrict__ g1,
                             const float* __restrict__ b1) {
    int row = blockIdx.x;
    int tid = threadIdx.x;
    int warp = tid >> 5, lane = tid & 31;
    __shared__ float sh[LL];
    __shared__ float mu_s, rstd_s;
    const float* xr = x + row * DD;
    // 8 warps, each handles 2 of the 16 outputs
    for (int l = warp; l < LL; l += 8) {
        float acc = 0.f;
        for (int d = lane; d < DD; d += 32) acc += xr[d] * pw[d * LL + l];
        #pragma unroll
        for (int o = 16; o; o >>= 1) acc += __shfl_down_sync(0xffffffffu, acc, o);
        if (lane == 0) sh[l] = acc + pb[l];
    }
    __syncthreads();
    if (tid == 0) {
        float m = 0.f;
        #pragma unroll
        for (int l = 0; l < LL; l++) m += sh[l];
        m *= (1.f / LL);
        float vv = 0.f;
        #pragma unroll
        for (int l = 0; l < LL; l++) { float t = sh[l] - m; vv += t * t; }
        vv *= (1.f / LL);
        mu_s = m; rstd_s = rsqrtf(vv + 1e-5f);
    }
    __syncthreads();
    if (tid < LL) {
        float y = (sh[tid] - mu_s) * rstd_s * g1[tid] + b1[tid];
        y = fmaxf(y, 0.f);
        g_xproj[row * LL + tid] = y;
        sh[tid] = y * y;
    }
    __syncthreads();
    if (tid == 0) {
        float nn = 0.f;
        #pragma unroll
        for (int l = 0; l < LL; l++) nn += sh[l];
        g_norms[row] = nn;
    }
}

// -------------------- stage 2: pi = sigmoid(relu(xp @ w1 + b1) @ w2 + b2) --------------------
__global__ void pi_kernel(const float* __restrict__ w1,
                          const float* __restrict__ b1,
                          const float* __restrict__ w2,
                          const float* __restrict__ b2) {
    int row = blockIdx.x, tid = threadIdx.x;
    __shared__ float xp[LL];
    __shared__ float red[8];
    if (tid < LL) xp[tid] = g_xproj[row * LL + tid];
    __syncthreads();
    float acc = 0.f;
    for (int d = tid; d < DD; d += 256) {
        float h = b1[d];
        #pragma unroll
        for (int l = 0; l < LL; l++) h += xp[l] * w1[l * DD + d];
        h = fmaxf(h, 0.f);
        acc += h * w2[d];
    }
    #pragma unroll
    for (int o = 16; o; o >>= 1) acc += __shfl_down_sync(0xffffffffu, acc, o);
    if ((tid & 31) == 0) red[tid >> 5] = acc;
    __syncthreads();
    if (tid == 0) {
        float s = 0.f;
        #pragma unroll
        for (int i = 0; i < 8; i++) s += red[i];
        s += b2[0];
        g_pi[row] = 1.f / (1.f + expf(-s));
    }
}

// -------------------- stage 3: K[i,j] = exp(-(ni+nj-2*xi.xj)/(4*eps)) --------------------
__global__ void k_kernel() {
    __shared__ float Ar[64][17];
    __shared__ float Ac[64][17];
    __shared__ float nr[64], nc[64];
    int ib = blockIdx.y * 64, jb = blockIdx.x * 64;
    int tid = threadIdx.x;
    {
        int r = tid >> 2, q4 = (tid & 3) * 4;
        float4 a = *(const float4*)&g_xproj[(ib + r) * LL + q4];
        Ar[r][q4 + 0] = a.x; Ar[r][q4 + 1] = a.y; Ar[r][q4 + 2] = a.z; Ar[r][q4 + 3] = a.w;
        float4 c = *(const float4*)&g_xproj[(jb + r) * LL + q4];
        Ac[r][q4 + 0] = c.x; Ac[r][q4 + 1] = c.y; Ac[r][q4 + 2] = c.z; Ac[r][q4 + 3] = c.w;
    }
    if (tid < 64) { nr[tid] = g_norms[ib + tid]; nc[tid] = g_norms[jb + tid]; }
    __syncthreads();
    int tx = tid & 15, ty = tid >> 4;
    float dot[4][4] = {};
    #pragma unroll
    for (int k = 0; k < LL; k++) {
        float a[4], c[4];
        #pragma unroll
        for (int i = 0; i < 4; i++) a[i] = Ar[ty * 4 + i][k];
        #pragma unroll
        for (int j = 0; j < 4; j++) c[j] = Ac[tx * 4 + j][k];
        #pragma unroll
        for (int i = 0; i < 4; i++)
            #pragma unroll
            for (int j = 0; j < 4; j++) dot[i][j] += a[i] * c[j];
    }
    const float cexp = -1.f / (4.f * EPSILON);
    #pragma unroll
    for (int i = 0; i < 4; i++) {
        int gi = ib + ty * 4 + i;
        float ni = nr[ty * 4 + i];
        float4 o;
        o.x = expf(cexp * (ni + nc[tx * 4 + 0] - 2.f * dot[i][0]));
        o.y = expf(cexp * (ni + nc[tx * 4 + 1] - 2.f * dot[i][1]));
        o.z = expf(cexp * (ni + nc[tx * 4 + 2] - 2.f * dot[i][2]));
        o.w = expf(cexp * (ni + nc[tx * 4 + 3] - 2.f * dot[i][3]));
        *(float4*)&g_K[gi * NN + jb + tx * 4] = o;
    }
}

// -------------------- reductions over K rows --------------------
__device__ __forceinline__ float block_reduce_256(float v, float* red) {
    #pragma unroll
    for (int o = 16; o; o >>= 1) v += __shfl_down_sync(0xffffffffu, v, o);
    int lane = threadIdx.x & 31, w = threadIdx.x >> 5;
    if (lane == 0) red[w] = v;
    __syncthreads();
    if (w == 0) {
        v = (lane < 8) ? red[lane] : 0.f;
        #pragma unroll
        for (int o = 4; o; o >>= 1) v += __shfl_down_sync(0xffffffffu, v, o);
    }
    return v;  // valid in thread 0
}

__global__ void q_kernel() {
    int row = blockIdx.x, tid = threadIdx.x;
    __shared__ float red[8];
    const float4* Kr = (const float4*)(g_K + row * NN);
    float acc = 0.f;
    for (int j = tid; j < NN / 4; j += 256) {
        float4 k4 = Kr[j];
        acc += k4.x + k4.y + k4.z + k4.w;
    }
    float s = block_reduce_256(acc, red);
    if (tid == 0) g_q[row] = s;
}

__global__ void v_kernel() {
    int i = blockIdx.x * blockDim.x + threadIdx.x;
    if (i < NN) g_v[i] = g_pi[i] / g_q[i];
}

__global__ void d_kernel() {
    int row = blockIdx.x, tid = threadIdx.x;
    __shared__ float red[8];
    const float* Kr = g_K + row * NN;
    float acc = 0.f;
    for (int j = tid; j < NN; j += 256) acc += Kr[j] * g_v[j];
    float s = block_reduce_256(acc, red);
    if (tid == 0) g_d[row] = s + 1e-5f;
}

// -------------------- generic tiled fp32 GEMM: C = A@B (+bias) (B rows optionally scaled) -----
template <bool SCALE_B, bool BIAS>
__global__ void sgemm_kernel(const float* __restrict__ A, const float* __restrict__ B,
                             const float* __restrict__ bias, const float* __restrict__ vs,
                             float* __restrict__ C, int M, int N, int K) {
    __shared__ float As[16][64];
    __shared__ float Bs[16][64];
    int tid = threadIdx.x;
    int rowBase = blockIdx.y * 64, colBase = blockIdx.x * 64;
    int tx = tid & 15, ty = tid >> 4;
    float acc[4][4] = {};
    int arow = tid >> 2, ak4 = (tid & 3) * 4;
    int brow = tid >> 4, bc4 = (tid & 15) * 4;
    for (int k0 = 0; k0 < K; k0 += 16) {
        float4 a = *(const float4*)&A[(size_t)(rowBase + arow) * K + k0 + ak4];
        As[ak4 + 0][arow] = a.x; As[ak4 + 1][arow] = a.y;
        As[ak4 + 2][arow] = a.z; As[ak4 + 3][arow] = a.w;
        float4 bv = *(const float4*)&B[(size_t)(k0 + brow) * N + colBase + bc4];
        if (SCALE_B) { float s = vs[k0 + brow]; bv.x *= s; bv.y *= s; bv.z *= s; bv.w *= s; }
        *(float4*)&Bs[brow][bc4] = bv;
        __syncthreads();
        #pragma unroll
        for (int k = 0; k < 16; k++) {
            float4 av = *(const float4*)&As[k][ty * 4];
            float4 bw = *(const float4*)&Bs[k][tx * 4];
            float aa[4] = {av.x, av.y, av.z, av.w};
            float bb[4] = {bw.x, bw.y, bw.z, bw.w};
            #pragma unroll
            for (int i = 0; i < 4; i++)
                #pragma unroll
                for (int j = 0; j < 4; j++) acc[i][j] += aa[i] * bb[j];
        }
        __syncthreads();
    }
    #pragma unroll
    for (int i = 0; i < 4; i++) {
        int r = rowBase + ty * 4 + i;
        float4 o;
        o.x = acc[i][0]; o.y = acc[i][1]; o.z = acc[i][2]; o.w = acc[i][3];
        if (BIAS) {
            o.x += bias[colBase + tx * 4 + 0];
            o.y += bias[colBase + tx * 4 + 1];
            o.z += bias[colBase + tx * 4 + 2];
            o.w += bias[colBase + tx * 4 + 3];
        }
        *(float4*)&C[(size_t)r * N + colBase + tx * 4] = o;
    }
}

// -------------------- final: mix + LayerNorm2 --------------------
__global__ void final_kernel(const float* __restrict__ x,
                             const float* __restrict__ dt,
                             const float* __restrict__ g2,
                             const float* __restrict__ b2,
                             float* __restrict__ out) {
    int row = blockIdx.x, tid = threadIdx.x;
    __shared__ float t2s[DD];
    __shared__ float red1[8], red2[8];
    __shared__ float mu_s, rstd_s;
    float dt0 = dt[0];
    float inv_ed = 1.f / (EPSILON * g_d[row]);
    float s1 = 0.f, s2 = 0.f;
    for (int d = tid; d < DD; d += 256) {
        float t = g_target[row * DD + d];
        float tt = dt0 * (g_S[row * DD + d] * inv_ed - t);
        float t2 = ALPHA * x[row * DD + d] + (1.f - ALPHA) * (t + 2.f * tt);
        t2s[d] = t2;
        s1 += t2;
        s2 += t2 * t2;
    }
    // two block reductions (separate scratch)
    #pragma unroll
    for (int o = 16; o; o >>= 1) {
        s1 += __shfl_down_sync(0xffffffffu, s1, o);
        s2 += __shfl_down_sync(0xffffffffu, s2, o);
    }
    int lane = tid & 31, w = tid >> 5;
    if (lane == 0) { red1[w] = s1; red2[w] = s2; }
    __syncthreads();
    if (tid == 0) {
        float a = 0.f, b = 0.f;
        #pragma unroll
        for (int i = 0; i < 8; i++) { a += red1[i]; b += red2[i]; }
        float mu = a / DD;
        float var = b / DD - mu * mu;
        mu_s = mu;
        rstd_s = rsqrtf(var + 1e-5f);
    }
    __syncthreads();
    float mu = mu_s, rstd = rstd_s;
    for (int d = tid; d < DD; d += 256) {
        out[row * DD + d] = (t2s[d] - mu) * rstd * g2[d] + b2[d];
    }
}

// -------------------- launch --------------------
extern "C" void kernel_launch(void* const* d_in, const int* in_sizes, int n_in,
                              void* d_out, int out_size) {
    const float* x      = (const float*)d_in[0];
    const float* proj_w = (const float*)d_in[1];
    const float* proj_b = (const float*)d_in[2];
    const float* ln1_g  = (const float*)d_in[3];
    const float* ln1_b  = (const float*)d_in[4];
    const float* pi_w1  = (const float*)d_in[5];
    const float* pi_b1  = (const float*)d_in[6];
    const float* pi_w2  = (const float*)d_in[7];
    const float* pi_b2  = (const float*)d_in[8];
    const float* dt     = (const float*)d_in[9];
    const float* f_w    = (const float*)d_in[10];
    const float* f_b    = (const float*)d_in[11];
    const float* ln2_g  = (const float*)d_in[12];
    const float* ln2_b  = (const float*)d_in[13];
    float* out = (float*)d_out;

    float *pK, *pT, *pS, *pV;
    cudaGetSymbolAddress((void**)&pK, g_K);
    cudaGetSymbolAddress((void**)&pT, g_target);
    cudaGetSymbolAddress((void**)&pS, g_S);
    cudaGetSymbolAddress((void**)&pV, g_v);

    xproj_kernel<<<NN, 256>>>(x, proj_w, proj_b, ln1_g, ln1_b);
    pi_kernel<<<NN, 256>>>(pi_w1, pi_b1, pi_w2, pi_b2);
    k_kernel<<<dim3(NN / 64, NN / 64), 256>>>();
    q_kernel<<<NN, 256>>>();
    v_kernel<<<(NN + 255) / 256, 256>>>();
    // target = x @ f_w + f_b   [2048,768] = [2048,768]@[768,768]
    sgemm_kernel<false, true><<<dim3(DD / 64, NN / 64), 256>>>(x, f_w, f_b, nullptr, pT, NN, DD, DD);
    d_kernel<<<NN, 256>>>();
    // S = K @ (v ⊙ target)    [2048,768] = [2048,2048]@[2048,768]
    sgemm_kernel<true, false><<<dim3(DD / 64, NN / 64), 256>>>(pK, pT, nullptr, pV, pS, NN, DD, NN);
    final_kernel<<<NN, 256>>>(x, dt, ln2_g, ln2_b, out);
}

// round 3
// speedup vs baseline: 2.3342x; 2.3342x over previous
#include <cuda_runtime.h>
#include <cstdint>
#include <math.h>

#define NN 2048
#define DD 768
#define LL 16
#define EPSILON 0.3f
#define ALPHA 0.7f

// ---- scratch (device globals; no allocation allowed) ----
__device__ float g_xproj[NN * LL];
__device__ float g_norms[NN];
__device__ float g_pi[NN];
__device__ float g_q[NN];
__device__ float g_v[NN];
__device__ float g_d[NN];
__device__ float g_K[NN * NN];        // 16 MB, tf32-rounded
__device__ float g_target[NN * DD];   // 6 MB (full fp32)
__device__ float g_S[NN * DD];        // 6 MB
__device__ float g_xr[NN * DD];       // tf32-rounded x
__device__ float g_fwr[DD * DD];      // tf32-rounded f_w ([K,N] natural layout)
__device__ float g_vt[NN * DD];       // tf32-rounded v[j]*target[j][d]

__device__ __forceinline__ float tf32r(float x) {
    uint32_t u;
    asm("cvt.rna.tf32.f32 %0, %1;" : "=r"(u) : "f"(x));
    return __uint_as_float(u);
}
__device__ __forceinline__ void cp16(uint32_t sdst, const float* g) {
    asm volatile("cp.async.cg.shared.global [%0], [%1], 16;" :: "r"(sdst), "l"(g) : "memory");
}
__device__ __forceinline__ void mma_tf32(float& c0, float& c1, float& c2, float& c3,
                                         uint32_t a0, uint32_t a1, uint32_t a2, uint32_t a3,
                                         uint32_t b0, uint32_t b1) {
    asm volatile(
        "mma.sync.aligned.m16n8k8.row.col.f32.tf32.tf32.f32 "
        "{%0,%1,%2,%3}, {%4,%5,%6,%7}, {%8,%9}, {%0,%1,%2,%3};"
        : "+f"(c0), "+f"(c1), "+f"(c2), "+f"(c3)
        : "r"(a0), "r"(a1), "r"(a2), "r"(a3), "r"(b0), "r"(b1));
}

// ======================= tf32 mma.sync GEMM =======================
// C[M,N] = A[M,K] @ B[K,N] (+bias). A row-major, B row-major [K,N].
// CTA tile 128x128, BK=32, 128 threads (4 warps, 2x2), warp tile 64x64.
// Smem per stage: A [128][36] floats (pad 4), B [32][136] floats (pad 8).
#define GEMM_STAGE_F 9216           // floats per stage (36864 B)
#define GEMM_B_OFF_F 4608           // B offset within stage (18432 B)
#define GEMM_SMEM (2 * 36864)

template <bool BIAS>
__global__ void __launch_bounds__(128, 1) mma_gemm(const float* __restrict__ A,
                                                   const float* __restrict__ B,
                                                   const float* __restrict__ bias,
                                                   float* __restrict__ C,
                                                   int N, int K) {
    extern __shared__ float smf[];
    uint32_t sbase = (uint32_t)__cvta_generic_to_shared(smf);
    int tid = threadIdx.x;
    int w = tid >> 5, lane = tid & 31;
    int wm = w & 1, wn = w >> 1;          // 2 x 2 warps
    int qid = lane >> 2, qlane = lane & 3;

    int rowBase = blockIdx.y * 128, colBase = blockIdx.x * 128;
    int NS = K >> 5;

    auto load_slab = [&](int s, int buf) {
        uint32_t st = sbase + buf * 36864u;
        int k0 = s * 32;
        #pragma unroll
        for (int i = 0; i < 8; i++) {           // A: 128 rows x 8 float4
            int idx = tid + i * 128;
            int r = idx >> 3, c4 = idx & 7;
            cp16(st + (uint32_t)(r * 144 + c4 * 16),
                 A + (size_t)(rowBase + r) * K + k0 + c4 * 4);
        }
        #pragma unroll
        for (int i = 0; i < 8; i++) {           // B: 32 rows x 32 float4
            int idx = tid + i * 128;
            int r = idx >> 5, c4 = idx & 31;
            cp16(st + 18432u + (uint32_t)(r * 544 + c4 * 16),
                 B + (size_t)(k0 + r) * N + colBase + c4 * 4);
        }
        asm volatile("cp.async.commit_group;" ::: "memory");
    };

    float acc[4][8][4];
    #pragma unroll
    for (int i = 0; i < 4; i++)
        #pragma unroll
        for (int j = 0; j < 8; j++)
            #pragma unroll
            for (int e = 0; e < 4; e++) acc[i][j][e] = 0.f;

    load_slab(0, 0);
    load_slab(1, 1);

    for (int s = 0; s < NS; s++) {
        int buf = s & 1;
        if (s < NS - 1) asm volatile("cp.async.wait_group 1;" ::: "memory");
        else            asm volatile("cp.async.wait_group 0;" ::: "memory");
        __syncthreads();

        const float* As = smf + buf * GEMM_STAGE_F;
        const float* Bs = As + GEMM_B_OFF_F;

        #pragma unroll
        for (int ks = 0; ks < 4; ks++) {
            int kk = ks * 8;
            uint32_t af[4][4], bf[8][2];
            #pragma unroll
            for (int mt = 0; mt < 4; mt++) {
                int r = wm * 64 + mt * 16 + qid;
                int c = kk + qlane;
                af[mt][0] = __float_as_uint(As[r * 36 + c]);
                af[mt][1] = __float_as_uint(As[(r + 8) * 36 + c]);
                af[mt][2] = __float_as_uint(As[r * 36 + c + 4]);
                af[mt][3] = __float_as_uint(As[(r + 8) * 36 + c + 4]);
            }
            #pragma unroll
            for (int nt = 0; nt < 8; nt++) {
                int n = wn * 64 + nt * 8 + qid;
                int k = kk + qlane;
                bf[nt][0] = __float_as_uint(Bs[k * 136 + n]);
                bf[nt][1] = __float_as_uint(Bs[(k + 4) * 136 + n]);
            }
            #pragma unroll
            for (int mt = 0; mt < 4; mt++)
                #pragma unroll
                for (int nt = 0; nt < 8; nt++)
                    mma_tf32(acc[mt][nt][0], acc[mt][nt][1], acc[mt][nt][2], acc[mt][nt][3],
                             af[mt][0], af[mt][1], af[mt][2], af[mt][3],
                             bf[nt][0], bf[nt][1]);
        }
        __syncthreads();
        if (s + 2 < NS) load_slab(s + 2, buf);
    }

    // epilogue
    #pragma unroll
    for (int mt = 0; mt < 4; mt++) {
        int r0 = rowBase + wm * 64 + mt * 16 + qid;
        #pragma unroll
        for (int nt = 0; nt < 8; nt++) {
            int col = colBase + wn * 64 + nt * 8 + 2 * qlane;
            float2 v0, v1;
            v0.x = acc[mt][nt][0]; v0.y = acc[mt][nt][1];
            v1.x = acc[mt][nt][2]; v1.y = acc[mt][nt][3];
            if (BIAS) {
                float bx = __ldg(bias + col), by = __ldg(bias + col + 1);
                v0.x += bx; v0.y += by; v1.x += bx; v1.y += by;
            }
            *(float2*)&C[(size_t)r0 * N + col] = v0;
            *(float2*)&C[(size_t)(r0 + 8) * N + col] = v1;
        }
    }
}

// ======================= stage 1: x_proj = relu(LN(x @ proj_w + proj_b)) =======================
// 128 blocks x 16 rows; thread (r,l) computes one output; LN via 16-lane shuffles.
__global__ void xproj_kernel(const float* __restrict__ x,
                             const float* __restrict__ pw,
                             const float* __restrict__ pb,
                             const float* __restrict__ g1,
                             const float* __restrict__ b1) {
    int r0 = blockIdx.x * 16;
    int tid = threadIdx.x;
    int r = tid >> 4, l = tid & 15;
    const float* xr = x + (size_t)(r0 + r) * DD;
    float acc = 0.f;
    #pragma unroll 4
    for (int d = 0; d < DD; d++) acc = fmaf(__ldg(xr + d), __ldg(pw + d * LL + l), acc);
    float y = acc + __ldg(pb + l);
    // mean / var over the 16 lanes of this row
    float s1 = y, s2 = y * y;
    #pragma unroll
    for (int o = 8; o; o >>= 1) {
        s1 += __shfl_xor_sync(0xffffffffu, s1, o, 16);
        s2 += __shfl_xor_sync(0xffffffffu, s2, o, 16);
    }
    float mu = s1 * (1.f / 16.f);
    float var = s2 * (1.f / 16.f) - mu * mu;
    float rstd = rsqrtf(var + 1e-5f);
    float yn = (y - mu) * rstd * __ldg(g1 + l) + __ldg(b1 + l);
    yn = fmaxf(yn, 0.f);
    g_xproj[(r0 + r) * LL + l] = yn;
    float n2 = yn * yn;
    #pragma unroll
    for (int o = 8; o; o >>= 1) n2 += __shfl_xor_sync(0xffffffffu, n2, o, 16);
    if (l == 0) g_norms[r0 + r] = n2;
}

// ======================= stage 2: pi head =======================
// 128 blocks x 16 rows; thread handles d-columns {tid, tid+256, tid+512}.
__global__ void pi_kernel(const float* __restrict__ w1,
                          const float* __restrict__ b1,
                          const float* __restrict__ w2,
                          const float* __restrict__ b2) {
    __shared__ float xp[16][LL];
    __shared__ float red[8][16];
    int r0 = blockIdx.x * 16;
    int tid = threadIdx.x;
    if (tid < 256 && tid < 16 * LL) xp[tid >> 4][tid & 15] = g_xproj[r0 * LL + tid];
    __syncthreads();
    float accr[16];
    #pragma unroll
    for (int r = 0; r < 16; r++) accr[r] = 0.f;
    #pragma unroll
    for (int c = 0; c < 3; c++) {
        int d = tid + c * 256;
        float col[LL];
        #pragma unroll
        for (int l = 0; l < LL; l++) col[l] = __ldg(w1 + l * DD + d);
        float bb = __ldg(b1 + d), w2d = __ldg(w2 + d);
        #pragma unroll
        for (int r = 0; r < 16; r++) {
            float h = bb;
            #pragma unroll
            for (int l = 0; l < LL; l++) h = fmaf(xp[r][l], col[l], h);
            accr[r] = fmaf(fmaxf(h, 0.f), w2d, accr[r]);
        }
    }
    int lane = tid & 31, w = tid >> 5;
    #pragma unroll
    for (int r = 0; r < 16; r++) {
        float s = accr[r];
        #pragma unroll
        for (int o = 16; o; o >>= 1) s += __shfl_xor_sync(0xffffffffu, s, o);
        if (lane == 0) red[w][r] = s;
    }
    __syncthreads();
    if (tid < 16) {
        float s = 0.f;
        #pragma unroll
        for (int i = 0; i < 8; i++) s += red[i][tid];
        s += __ldg(b2);
        g_pi[r0 + tid] = 1.f / (1.f + __expf(-s));
    }
}

// ======================= stage 3: K tile kernel =======================
__global__ void k_kernel() {
    __shared__ float Ar[64][17];
    __shared__ float Ac[64][17];
    __shared__ float nr[64], nc[64];
    int ib = blockIdx.y * 64, jb = blockIdx.x * 64;
    int tid = threadIdx.x;
    {
        int r = tid >> 2, q4 = (tid & 3) * 4;
        float4 a = *(const float4*)&g_xproj[(ib + r) * LL + q4];
        Ar[r][q4 + 0] = a.x; Ar[r][q4 + 1] = a.y; Ar[r][q4 + 2] = a.z; Ar[r][q4 + 3] = a.w;
        float4 c = *(const float4*)&g_xproj[(jb + r) * LL + q4];
        Ac[r][q4 + 0] = c.x; Ac[r][q4 + 1] = c.y; Ac[r][q4 + 2] = c.z; Ac[r][q4 + 3] = c.w;
    }
    if (tid < 64) { nr[tid] = g_norms[ib + tid]; nc[tid] = g_norms[jb + tid]; }
    __syncthreads();
    int tx = tid & 15, ty = tid >> 4;
    float dot[4][4] = {};
    #pragma unroll
    for (int k = 0; k < LL; k++) {
        float a[4], c[4];
        #pragma unroll
        for (int i = 0; i < 4; i++) a[i] = Ar[ty * 4 + i][k];
        #pragma unroll
        for (int j = 0; j < 4; j++) c[j] = Ac[tx * 4 + j][k];
        #pragma unroll
        for (int i = 0; i < 4; i++)
            #pragma unroll
            for (int j = 0; j < 4; j++) dot[i][j] = fmaf(a[i], c[j], dot[i][j]);
    }
    const float cexp = -1.f / (4.f * EPSILON);
    #pragma unroll
    for (int i = 0; i < 4; i++) {
        int gi = ib + ty * 4 + i;
        float ni = nr[ty * 4 + i];
        float4 o;
        o.x = tf32r(__expf(cexp * (ni + nc[tx * 4 + 0] - 2.f * dot[i][0])));
        o.y = tf32r(__expf(cexp * (ni + nc[tx * 4 + 1] - 2.f * dot[i][1])));
        o.z = tf32r(__expf(cexp * (ni + nc[tx * 4 + 2] - 2.f * dot[i][2])));
        o.w = tf32r(__expf(cexp * (ni + nc[tx * 4 + 3] - 2.f * dot[i][3])));
        *(float4*)&g_K[gi * NN + jb + tx * 4] = o;
    }
}

// ======================= q / v / d =======================
// warp-per-row reductions; 16 float4 per lane for MLP.
__global__ void q_kernel() {
    int w = threadIdx.x >> 5, lane = threadIdx.x & 31;
    int row = blockIdx.x * 8 + w;
    const float4* Kr = (const float4*)(g_K + (size_t)row * NN);
    float acc = 0.f;
    #pragma unroll
    for (int i = 0; i < 16; i++) {
        float4 k4 = Kr[lane + i * 32];
        acc += (k4.x + k4.y) + (k4.z + k4.w);
    }
    #pragma unroll
    for (int o = 16; o; o >>= 1) acc += __shfl_xor_sync(0xffffffffu, acc, o);
    if (lane == 0) g_q[row] = acc;
}

__global__ void v_kernel() {
    int i = blockIdx.x * blockDim.x + threadIdx.x;
    if (i < NN) g_v[i] = g_pi[i] / g_q[i];
}

__global__ void d_kernel() {
    int w = threadIdx.x >> 5, lane = threadIdx.x & 31;
    int row = blockIdx.x * 8 + w;
    const float4* Kr = (const float4*)(g_K + (size_t)row * NN);
    const float4* Vr = (const float4*)g_v;
    float acc = 0.f;
    #pragma unroll
    for (int i = 0; i < 16; i++) {
        float4 k4 = Kr[lane + i * 32];
        float4 v4 = Vr[lane + i * 32];
        acc += k4.x * v4.x + k4.y * v4.y + k4.z * v4.z + k4.w * v4.w;
    }
    #pragma unroll
    for (int o = 16; o; o >>= 1) acc += __shfl_xor_sync(0xffffffffu, acc, o);
    if (lane == 0) g_d[row] = acc + 1e-5f;
}

// ======================= elementwise rounding producers =======================
__global__ void roundx_kernel(const float* __restrict__ x, float* __restrict__ o) {
    int i = blockIdx.x * 256 + threadIdx.x;
    float4 a = ((const float4*)x)[i];
    a.x = tf32r(a.x); a.y = tf32r(a.y); a.z = tf32r(a.z); a.w = tf32r(a.w);
    ((float4*)o)[i] = a;
}

// g_vt[j][d] = tf32r(v[j] * target[j][d]);  192 float4 per row
__global__ void vt_kernel() {
    int i = blockIdx.x * 256 + threadIdx.x;
    int row = i / 192;
    float s = g_v[row];
    float4 a = ((const float4*)g_target)[i];
    a.x = tf32r(a.x * s); a.y = tf32r(a.y * s); a.z = tf32r(a.z * s); a.w = tf32r(a.w * s);
    ((float4*)g_vt)[i] = a;
}

// ======================= final: mix + LayerNorm2 =======================
__global__ void final_kernel(const float* __restrict__ x,
                             const float* __restrict__ dt,
                             const float* __restrict__ g2,
                             const float* __restrict__ b2,
                             float* __restrict__ out) {
    int row = blockIdx.x, tid = threadIdx.x;
    __shared__ float t2s[DD];
    __shared__ float red1[8], red2[8];
    __shared__ float mu_s, rstd_s;
    float dt0 = __ldg(dt);
    float inv_ed = 1.f / (EPSILON * g_d[row]);
    float s1 = 0.f, s2 = 0.f;
    for (int d = tid; d < DD; d += 256) {
        float t = g_target[row * DD + d];
        float tt = dt0 * (g_S[row * DD + d] * inv_ed - t);
        float t2 = ALPHA * __ldg(x + row * DD + d) + (1.f - ALPHA) * (t + 2.f * tt);
        t2s[d] = t2;
        s1 += t2;
        s2 += t2 * t2;
    }
    #pragma unroll
    for (int o = 16; o; o >>= 1) {
        s1 += __shfl_xor_sync(0xffffffffu, s1, o);
        s2 += __shfl_xor_sync(0xffffffffu, s2, o);
    }
    int lane = tid & 31, w = tid >> 5;
    if (lane == 0) { red1[w] = s1; red2[w] = s2; }
    __syncthreads();
    if (tid == 0) {
        float a = 0.f, b = 0.f;
        #pragma unroll
        for (int i = 0; i < 8; i++) { a += red1[i]; b += red2[i]; }
        float mu = a / DD;
        float var = b / DD - mu * mu;
        mu_s = mu;
        rstd_s = rsqrtf(var + 1e-5f);
    }
    __syncthreads();
    float mu = mu_s, rstd = rstd_s;
    for (int d = tid; d < DD; d += 256) {
        out[row * DD + d] = (t2s[d] - mu) * rstd * __ldg(g2 + d) + __ldg(b2 + d);
    }
}

// ======================= launch =======================
extern "C" void kernel_launch(void* const* d_in, const int* in_sizes, int n_in,
                              void* d_out, int out_size) {
    const float* x      = (const float*)d_in[0];
    const float* proj_w = (const float*)d_in[1];
    const float* proj_b = (const float*)d_in[2];
    const float* ln1_g  = (const float*)d_in[3];
    const float* ln1_b  = (const float*)d_in[4];
    const float* pi_w1  = (const float*)d_in[5];
    const float* pi_b1  = (const float*)d_in[6];
    const float* pi_w2  = (const float*)d_in[7];
    const float* pi_b2  = (const float*)d_in[8];
    const float* dt     = (const float*)d_in[9];
    const float* f_w    = (const float*)d_in[10];
    const float* f_b    = (const float*)d_in[11];
    const float* ln2_g  = (const float*)d_in[12];
    const float* ln2_b  = (const float*)d_in[13];
    float* out = (float*)d_out;

    float *pK, *pT, *pS, *pXR, *pFWR, *pVT;
    cudaGetSymbolAddress((void**)&pK, g_K);
    cudaGetSymbolAddress((void**)&pT, g_target);
    cudaGetSymbolAddress((void**)&pS, g_S);
    cudaGetSymbolAddress((void**)&pXR, g_xr);
    cudaGetSymbolAddress((void**)&pFWR, g_fwr);
    cudaGetSymbolAddress((void**)&pVT, g_vt);

    cudaFuncSetAttribute(mma_gemm<true>, cudaFuncAttributeMaxDynamicSharedMemorySize, GEMM_SMEM);
    cudaFuncSetAttribute(mma_gemm<false>, cudaFuncAttributeMaxDynamicSharedMemorySize, GEMM_SMEM);

    // operand rounding
    roundx_kernel<<<NN * DD / 1024, 256>>>(x, pXR);
    roundx_kernel<<<DD * DD / 1024, 256>>>(f_w, pFWR);

    // projection + heads
    xproj_kernel<<<NN / 16, 256>>>(x, proj_w, proj_b, ln1_g, ln1_b);
    pi_kernel<<<NN / 16, 256>>>(pi_w1, pi_b1, pi_w2, pi_b2);

    // target = x @ f_w + f_b     [2048,768] = [2048,768] @ [768,768]
    mma_gemm<true><<<dim3(DD / 128, NN / 128), 128, GEMM_SMEM>>>(pXR, pFWR, f_b, pT, DD, DD);

    // kernel matrix + reductions
    k_kernel<<<dim3(NN / 64, NN / 64), 256>>>();
    q_kernel<<<NN / 8, 256>>>();
    v_kernel<<<NN / 256, 256>>>();
    d_kernel<<<NN / 8, 256>>>();

    // B operand for S-GEMM: v[j] * target[j][d], rounded
    vt_kernel<<<NN * DD / 1024, 256>>>();

    // S = K @ (v*target)         [2048,768] = [2048,2048] @ [2048,768]
    mma_gemm<false><<<dim3(DD / 128, NN / 128), 128, GEMM_SMEM>>>(pK, pVT, nullptr, pS, DD, NN);

    final_kernel<<<NN, 256>>>(x, dt, ln2_g, ln2_b, out);
}

// round 7
// speedup vs baseline: 3.6353x; 1.5574x over previous
#include <cuda_runtime.h>
#include <cuda_fp16.h>
#include <cstdint>
#include <math.h>

#define NN 2048
#define DD 768
#define LL 16
#define EPSILON 0.3f
#define ALPHA 0.7f

// ---- scratch (device globals; no allocation allowed) ----
__device__ float  g_xproj[NN * LL];
__device__ float  g_norms[NN];
__device__ float  g_pi[NN];
__device__ float  g_q[NN];
__device__ float  g_v[NN];
__device__ float  g_d[NN];
__device__ __half g_Kh[NN * NN];       // 8 MB fp16 kernel matrix
__device__ float  g_target[NN * DD];   // fp32
__device__ float  g_S[NN * DD];        // fp32
__device__ __half g_xh[NN * DD];       // fp16 x
__device__ __half g_fwh[DD * DD];      // fp16 f_w  [K,N]
__device__ __half g_vth[NN * DD];      // fp16 v[j]*target[j][d]

__device__ __forceinline__ void cp16(uint32_t sdst, const void* g) {
    asm volatile("cp.async.cg.shared.global [%0], [%1], 16;" :: "r"(sdst), "l"(g) : "memory");
}

// ======================= fp16 mma.sync GEMM =======================
// C[M,N](fp32) = A[M,K](half) @ B[K,N](half) (+bias)
// CTA 128x128, BK=32, 256 threads (8 warps: 2 in M x 4 in N), warp tile 64x32.
// Smem/stage: A 128 rows x 40 half (pad 8) = 10240B; B 32 rows x 136 half = 8704B.
#define HG_STAGE 18944u
#define HG_SMEM (4 * 18944)

template <bool BIAS>
__global__ void __launch_bounds__(256, 1) hgemm(const __half* __restrict__ A,
                                                const __half* __restrict__ B,
                                                const float* __restrict__ bias,
                                                float* __restrict__ C,
                                                int N, int K) {
    extern __shared__ char smc[];
    uint32_t sbase = (uint32_t)__cvta_generic_to_shared(smc);
    int tid = threadIdx.x;
    int w = tid >> 5, lane = tid & 31;
    int wm = w & 1, wn = w >> 1;  // 2 x 4
    int rowBase = blockIdx.y * 128, colBase = blockIdx.x * 128;
    int NS = K >> 5;

    auto load_slab = [&](int s) {
        uint32_t st = sbase + (uint32_t)(s & 3) * HG_STAGE;
        int k0 = s * 32;
        #pragma unroll
        for (int i = 0; i < 2; i++) {  // A: 128 rows x 4 chunks (16B)
            int idx = tid + i * 256;
            int r = idx >> 2, c = idx & 3;
            cp16(st + (uint32_t)(r * 80 + c * 16),
                 A + (size_t)(rowBase + r) * K + k0 + c * 8);
        }
        #pragma unroll
        for (int i = 0; i < 2; i++) {  // B: 32 rows x 16 chunks
            int idx = tid + i * 256;
            int r = idx >> 4, c = idx & 15;
            cp16(st + 10240u + (uint32_t)(r * 272 + c * 16),
                 B + (size_t)(k0 + r) * N + colBase + c * 8);
        }
        asm volatile("cp.async.commit_group;" ::: "memory");
    };

    float acc[4][4][4];
    #pragma unroll
    for (int i = 0; i < 4; i++)
        #pragma unroll
        for (int j = 0; j < 4; j++)
            #pragma unroll
            for (int e = 0; e < 4; e++) acc[i][j][e] = 0.f;

    load_slab(0); load_slab(1); load_slab(2);

    for (int s = 0; s < NS; s++) {
        asm volatile("cp.async.wait_group 2;" ::: "memory");
        __syncthreads();
        uint32_t sA = sbase + (uint32_t)(s & 3) * HG_STAGE;
        uint32_t sB = sA + 10240u;

        #pragma unroll
        for (int ks = 0; ks < 2; ks++) {
            int kk = ks * 16;
            uint32_t af[4][4];
            #pragma unroll
            for (int mt = 0; mt < 4; mt++) {
                int row = wm * 64 + mt * 16 + (lane & 15);
                int col = kk + ((lane >> 4) << 3);
                uint32_t ad = sA + (uint32_t)(row * 80 + col * 2);
                asm volatile("ldmatrix.sync.aligned.m8n8.x4.shared.b16 {%0,%1,%2,%3}, [%4];"
                             : "=r"(af[mt][0]), "=r"(af[mt][1]), "=r"(af[mt][2]), "=r"(af[mt][3])
                             : "r"(ad));
            }
            uint32_t bf[2][4];
            #pragma unroll
            for (int nt = 0; nt < 2; nt++) {
                int krow = kk + (((lane >> 3) & 1) << 3) + (lane & 7);
                int ncol = wn * 32 + nt * 16 + ((lane >> 4) << 3);
                uint32_t ad = sB + (uint32_t)(krow * 272 + ncol * 2);
                asm volatile("ldmatrix.sync.aligned.m8n8.x4.trans.shared.b16 {%0,%1,%2,%3}, [%4];"
                             : "=r"(bf[nt][0]), "=r"(bf[nt][1]), "=r"(bf[nt][2]), "=r"(bf[nt][3])
                             : "r"(ad));
            }
            #pragma unroll
            for (int mt = 0; mt < 4; mt++)
                #pragma unroll
                for (int nt = 0; nt < 2; nt++)
                    #pragma unroll
                    for (int h = 0; h < 2; h++) {
                        float* c = acc[mt][nt * 2 + h];
                        asm volatile(
                            "mma.sync.aligned.m16n8k16.row.col.f32.f16.f16.f32 "
                            "{%0,%1,%2,%3}, {%4,%5,%6,%7}, {%8,%9}, {%0,%1,%2,%3};"
                            : "+f"(c[0]), "+f"(c[1]), "+f"(c[2]), "+f"(c[3])
                            : "r"(af[mt][0]), "r"(af[mt][1]), "r"(af[mt][2]), "r"(af[mt][3]),
                              "r"(bf[nt][2 * h]), "r"(bf[nt][2 * h + 1]));
                    }
        }
        if (s + 3 < NS) load_slab(s + 3);
        else asm volatile("cp.async.commit_group;" ::: "memory");
    }
    asm volatile("cp.async.wait_group 0;" ::: "memory");

    // epilogue
    int qid = lane >> 2, qlane = lane & 3;
    #pragma unroll
    for (int mt = 0; mt < 4; mt++) {
        int r0 = rowBase + wm * 64 + mt * 16 + qid;
        #pragma unroll
        for (int nb = 0; nb < 4; nb++) {
            int col = colBase + wn * 32 + nb * 8 + qlane * 2;
            float2 v0, v1;
            v0.x = acc[mt][nb][0]; v0.y = acc[mt][nb][1];
            v1.x = acc[mt][nb][2]; v1.y = acc[mt][nb][3];
            if (BIAS) {
                float bx = __ldg(bias + col), by = __ldg(bias + col + 1);
                v0.x += bx; v0.y += by; v1.x += bx; v1.y += by;
            }
            *(float2*)&C[(size_t)r0 * N + col] = v0;
            *(float2*)&C[(size_t)(r0 + 8) * N + col] = v1;
        }
    }
}

// ======================= stage 1: x_proj, warp per row =======================
__global__ void xproj_kernel(const float* __restrict__ x,
                             const float* __restrict__ pw,
                             const float* __restrict__ pb,
                             const float* __restrict__ g1,
                             const float* __restrict__ b1) {
    int w = threadIdx.x >> 5, lane = threadIdx.x & 31;
    int row = blockIdx.x * 8 + w;
    const float* xr = x + (size_t)row * DD;
    float acc[LL];
    #pragma unroll
    for (int l = 0; l < LL; l++) acc[l] = 0.f;
    #pragma unroll 4
    for (int i = 0; i < DD / 32; i++) {
        int d = lane + i * 32;
        float xd = __ldg(xr + d);
        const float4* pwr = (const float4*)(pw + d * LL);
        #pragma unroll
        for (int q4 = 0; q4 < 4; q4++) {
            float4 wv = __ldg(pwr + q4);
            acc[q4 * 4 + 0] = fmaf(xd, wv.x, acc[q4 * 4 + 0]);
            acc[q4 * 4 + 1] = fmaf(xd, wv.y, acc[q4 * 4 + 1]);
            acc[q4 * 4 + 2] = fmaf(xd, wv.z, acc[q4 * 4 + 2]);
            acc[q4 * 4 + 3] = fmaf(xd, wv.w, acc[q4 * 4 + 3]);
        }
    }
    // butterfly: every lane ends with all 16 sums
    #pragma unroll
    for (int l = 0; l < LL; l++) {
        #pragma unroll
        for (int o = 16; o; o >>= 1) acc[l] += __shfl_xor_sync(0xffffffffu, acc[l], o);
    }
    float y[LL];
    float s1 = 0.f, s2 = 0.f;
    #pragma unroll
    for (int l = 0; l < LL; l++) {
        y[l] = acc[l] + __ldg(pb + l);
        s1 += y[l];
    }
    float mu = s1 * (1.f / LL);
    #pragma unroll
    for (int l = 0; l < LL; l++) { float t = y[l] - mu; s2 += t * t; }
    float rstd = rsqrtf(s2 * (1.f / LL) + 1e-5f);
    float n2 = 0.f;
    #pragma unroll
    for (int l = 0; l < LL; l++) {
        float yn = fmaxf((y[l] - mu) * rstd * __ldg(g1 + l) + __ldg(b1 + l), 0.f);
        y[l] = yn;
        n2 += yn * yn;
    }
    if (lane < LL) g_xproj[row * LL + lane] = y[lane];
    if (lane == 16) g_norms[row] = n2;
}

// ======================= stage 2: pi head (8 rows / block) =======================
__global__ void pi_kernel(const float* __restrict__ w1,
                          const float* __restrict__ b1,
                          const float* __restrict__ w2,
                          const float* __restrict__ b2) {
    __shared__ float xp[8][LL];
    __shared__ float red[8][8];
    int r0 = blockIdx.x * 8;
    int tid = threadIdx.x;
    if (tid < 8 * LL) xp[tid >> 4][tid & 15] = g_xproj[r0 * LL + tid];
    __syncthreads();
    float accr[8];
    #pragma unroll
    for (int r = 0; r < 8; r++) accr[r] = 0.f;
    #pragma unroll
    for (int c = 0; c < 3; c++) {
        int d = tid + c * 256;
        float col[LL];
        #pragma unroll
        for (int l = 0; l < LL; l++) col[l] = __ldg(w1 + l * DD + d);
        float bb = __ldg(b1 + d), w2d = __ldg(w2 + d);
        #pragma unroll
        for (int r = 0; r < 8; r++) {
            float h = bb;
            #pragma unroll
            for (int l = 0; l < LL; l++) h = fmaf(xp[r][l], col[l], h);
            accr[r] = fmaf(fmaxf(h, 0.f), w2d, accr[r]);
        }
    }
    int lane = tid & 31, w = tid >> 5;
    #pragma unroll
    for (int r = 0; r < 8; r++) {
        float s = accr[r];
        #pragma unroll
        for (int o = 16; o; o >>= 1) s += __shfl_xor_sync(0xffffffffu, s, o);
        if (lane == 0) red[w][r] = s;
    }
    __syncthreads();
    if (tid < 8) {
        float s = 0.f;
        #pragma unroll
        for (int i = 0; i < 8; i++) s += red[i][tid];
        s += __ldg(b2);
        g_pi[r0 + tid] = 1.f / (1.f + __expf(-s));
    }
}

// ======================= stage 3: K tiles (fp16 out) =======================
__global__ void k_kernel() {
    __shared__ float Ar[64][17];
    __shared__ float Ac[64][17];
    __shared__ float nr[64], nc[64];
    int ib = blockIdx.y * 64, jb = blockIdx.x * 64;
    int tid = threadIdx.x;
    {
        int r = tid >> 2, q4 = (tid & 3) * 4;
        float4 a = *(const float4*)&g_xproj[(ib + r) * LL + q4];
        Ar[r][q4 + 0] = a.x; Ar[r][q4 + 1] = a.y; Ar[r][q4 + 2] = a.z; Ar[r][q4 + 3] = a.w;
        float4 c = *(const float4*)&g_xproj[(jb + r) * LL + q4];
        Ac[r][q4 + 0] = c.x; Ac[r][q4 + 1] = c.y; Ac[r][q4 + 2] = c.z; Ac[r][q4 + 3] = c.w;
    }
    if (tid < 64) { nr[tid] = g_norms[ib + tid]; nc[tid] = g_norms[jb + tid]; }
    __syncthreads();
    int tx = tid & 15, ty = tid >> 4;
    float dot[4][4] = {};
    #pragma unroll
    for (int k = 0; k < LL; k++) {
        float a[4], c[4];
        #pragma unroll
        for (int i = 0; i < 4; i++) a[i] = Ar[ty * 4 + i][k];
        #pragma unroll
        for (int j = 0; j < 4; j++) c[j] = Ac[tx * 4 + j][k];
        #pragma unroll
        for (int i = 0; i < 4; i++)
            #pragma unroll
            for (int j = 0; j < 4; j++) dot[i][j] = fmaf(a[i], c[j], dot[i][j]);
    }
    const float cexp = -1.f / (4.f * EPSILON);
    #pragma unroll
    for (int i = 0; i < 4; i++) {
        int gi = ib + ty * 4 + i;
        float ni = nr[ty * 4 + i];
        float e0 = __expf(cexp * (ni + nc[tx * 4 + 0] - 2.f * dot[i][0]));
        float e1 = __expf(cexp * (ni + nc[tx * 4 + 1] - 2.f * dot[i][1]));
        float e2 = __expf(cexp * (ni + nc[tx * 4 + 2] - 2.f * dot[i][2]));
        float e3 = __expf(cexp * (ni + nc[tx * 4 + 3] - 2.f * dot[i][3]));
        __half2 p0 = __floats2half2_rn(e0, e1);
        __half2 p1 = __floats2half2_rn(e2, e3);
        uint2 u;
        u.x = *(unsigned*)&p0;
        u.y = *(unsigned*)&p1;
        *(uint2*)&g_Kh[(size_t)gi * NN + jb + tx * 4] = u;
    }
}

// ======================= q / v / d (half K) =======================
__global__ void q_kernel() {
    int w = threadIdx.x >> 5, lane = threadIdx.x & 31;
    int row = blockIdx.x * 8 + w;
    const uint4* Kr = (const uint4*)(g_Kh + (size_t)row * NN);
    float acc = 0.f;
    #pragma unroll
    for (int i = 0; i < 8; i++) {
        uint4 u = Kr[lane + i * 32];
        float2 f0 = __half22float2(*(__half2*)&u.x);
        float2 f1 = __half22float2(*(__half2*)&u.y);
        float2 f2 = __half22float2(*(__half2*)&u.z);
        float2 f3 = __half22float2(*(__half2*)&u.w);
        acc += (f0.x + f0.y) + (f1.x + f1.y) + (f2.x + f2.y) + (f3.x + f3.y);
    }
    #pragma unroll
    for (int o = 16; o; o >>= 1) acc += __shfl_xor_sync(0xffffffffu, acc, o);
    if (lane == 0) g_q[row] = acc;
}

__global__ void v_kernel() {
    int i = blockIdx.x * blockDim.x + threadIdx.x;
    if (i < NN) g_v[i] = g_pi[i] / g_q[i];
}

__global__ void d_kernel() {
    int w = threadIdx.x >> 5, lane = threadIdx.x & 31;
    int row = blockIdx.x * 8 + w;
    const uint4* Kr = (const uint4*)(g_Kh + (size_t)row * NN);
    const float4* Vr = (const float4*)g_v;
    float acc = 0.f;
    #pragma unroll
    for (int i = 0; i < 8; i++) {
        int j = lane + i * 32;
        uint4 u = Kr[j];
        float4 va = Vr[2 * j], vb = Vr[2 * j + 1];
        float2 f0 = __half22float2(*(__half2*)&u.x);
        float2 f1 = __half22float2(*(__half2*)&u.y);
        float2 f2 = __half22float2(*(__half2*)&u.z);
        float2 f3 = __half22float2(*(__half2*)&u.w);
        acc += f0.x * va.x + f0.y * va.y + f1.x * va.z + f1.y * va.w;
        acc += f2.x * vb.x + f2.y * vb.y + f3.x * vb.z + f3.y * vb.w;
    }
    #pragma unroll
    for (int o = 16; o; o >>= 1) acc += __shfl_xor_sync(0xffffffffu, acc, o);
    if (lane == 0) g_d[row] = acc + 1e-5f;
}

// ======================= fp32 -> fp16 producers =======================
__global__ void tohalf_kernel(const float* __restrict__ src, __half* __restrict__ dst) {
    int i = blockIdx.x * 256 + threadIdx.x;
    float4 a = ((const float4*)src)[i];
    __half2 h0 = __floats2half2_rn(a.x, a.y);
    __half2 h1 = __floats2half2_rn(a.z, a.w);
    uint2 u;
    u.x = *(unsigned*)&h0;
    u.y = *(unsigned*)&h1;
    ((uint2*)dst)[i] = u;
}

// g_vth[j][d] = half(v[j] * target[j][d])
__global__ void vth_kernel() {
    int i = blockIdx.x * 256 + threadIdx.x;
    int row = i / (DD / 4);
    float s = g_v[row];
    float4 a = ((const float4*)g_target)[i];
    __half2 h0 = __floats2half2_rn(a.x * s, a.y * s);
    __half2 h1 = __floats2half2_rn(a.z * s, a.w * s);
    uint2 u;
    u.x = *(unsigned*)&h0;
    u.y = *(unsigned*)&h1;
    ((uint2*)g_vth)[i] = u;
}

// ======================= final: mix + LayerNorm2 =======================
__global__ void final_kernel(const float* __restrict__ x,
                             const float* __restrict__ dt,
                             const float* __restrict__ g2,
                             const float* __restrict__ b2,
                             float* __restrict__ out) {
    int row = blockIdx.x, tid = threadIdx.x;
    __shared__ float t2s[DD];
    __shared__ float red1[8], red2[8];
    __shared__ float mu_s, rstd_s;
    float dt0 = __ldg(dt);
    float inv_ed = 1.f / (EPSILON * g_d[row]);
    float s1 = 0.f, s2 = 0.f;
    for (int d = tid; d < DD; d += 256) {
        float t = g_target[row * DD + d];
        float tt = dt0 * (g_S[row * DD + d] * inv_ed - t);
        float t2 = ALPHA * __ldg(x + row * DD + d) + (1.f - ALPHA) * (t + 2.f * tt);
        t2s[d] = t2;
        s1 += t2;
        s2 += t2 * t2;
    }
    #pragma unroll
    for (int o = 16; o; o >>= 1) {
        s1 += __shfl_xor_sync(0xffffffffu, s1, o);
        s2 += __shfl_xor_sync(0xffffffffu, s2, o);
    }
    int lane = tid & 31, w = tid >> 5;
    if (lane == 0) { red1[w] = s1; red2[w] = s2; }
    __syncthreads();
    if (tid == 0) {
        float a = 0.f, b = 0.f;
        #pragma unroll
        for (int i = 0; i < 8; i++) { a += red1[i]; b += red2[i]; }
        float mu = a / DD;
        float var = b / DD - mu * mu;
        mu_s = mu;
        rstd_s = rsqrtf(var + 1e-5f);
    }
    __syncthreads();
    float mu = mu_s, rstd = rstd_s;
    for (int d = tid; d < DD; d += 256) {
        out[row * DD + d] = (t2s[d] - mu) * rstd * __ldg(g2 + d) + __ldg(b2 + d);
    }
}

// ======================= launch =======================
extern "C" void kernel_launch(void* const* d_in, const int* in_sizes, int n_in,
                              void* d_out, int out_size) {
    const float* x      = (const float*)d_in[0];
    const float* proj_w = (const float*)d_in[1];
    const float* proj_b = (const float*)d_in[2];
    const float* ln1_g  = (const float*)d_in[3];
    const float* ln1_b  = (const float*)d_in[4];
    const float* pi_w1  = (const float*)d_in[5];
    const float* pi_b1  = (const float*)d_in[6];
    const float* pi_w2  = (const float*)d_in[7];
    const float* pi_b2  = (const float*)d_in[8];
    const float* dt     = (const float*)d_in[9];
    const float* f_w    = (const float*)d_in[10];
    const float* f_b    = (const float*)d_in[11];
    const float* ln2_g  = (const float*)d_in[12];
    const float* ln2_b  = (const float*)d_in[13];
    float* out = (float*)d_out;

    float *pT, *pS;
    __half *pKh, *pXH, *pFWH, *pVTH;
    cudaGetSymbolAddress((void**)&pT, g_target);
    cudaGetSymbolAddress((void**)&pS, g_S);
    cudaGetSymbolAddress((void**)&pKh, g_Kh);
    cudaGetSymbolAddress((void**)&pXH, g_xh);
    cudaGetSymbolAddress((void**)&pFWH, g_fwh);
    cudaGetSymbolAddress((void**)&pVTH, g_vth);

    cudaFuncSetAttribute(hgemm<true>, cudaFuncAttributeMaxDynamicSharedMemorySize, HG_SMEM);
    cudaFuncSetAttribute(hgemm<false>, cudaFuncAttributeMaxDynamicSharedMemorySize, HG_SMEM);

    // fp16 operand producers
    tohalf_kernel<<<NN * DD / 1024, 256>>>(x, pXH);
    tohalf_kernel<<<DD * DD / 1024, 256>>>(f_w, pFWH);

    // projection + pi head
    xproj_kernel<<<NN / 8, 256>>>(x, proj_w, proj_b, ln1_g, ln1_b);
    pi_kernel<<<NN / 8, 256>>>(pi_w1, pi_b1, pi_w2, pi_b2);

    // target = x @ f_w + f_b   [2048,768]
    hgemm<true><<<dim3(DD / 128, NN / 128), 256, HG_SMEM>>>(pXH, pFWH, f_b, pT, DD, DD);

    // kernel matrix + reductions
    k_kernel<<<dim3(NN / 64, NN / 64), 256>>>();
    q_kernel<<<NN / 8, 256>>>();
    v_kernel<<<NN / 256, 256>>>();
    d_kernel<<<NN / 8, 256>>>();

    // B operand for S-GEMM
    vth_kernel<<<NN * DD / 1024, 256>>>();

    // S = K @ (v*target)       [2048,768] = [2048,2048] @ [2048,768]
    hgemm<false><<<dim3(DD / 128, NN / 128), 256, HG_SMEM>>>(pKh, pVTH, nullptr, pS, DD, NN);

    final_kernel<<<NN, 256>>>(x, dt, ln2_g, ln2_b, out);
}